// round 14
// baseline (speedup 1.0000x reference)
#include <cuda_runtime.h>
#include <math.h>

#define H      2048
#define HH     1024
#define NB     4
#define S      4096
#define NROWS  (NB*S)          // 16384 rows per matrix
#define SCHUNK 32
#define NCHUNK (S/SCHUNK)      // 128
#define TILE_R 32
#define NTILE  (NROWS/TILE_R)  // 512 tiles per half
#define CTAS_HALF 152
#define MT     256             // main kernel threads

typedef unsigned long long ull;

// ---------------- packed f32x2 helpers ----------------------------------
__device__ __forceinline__ ull pack2(float lo, float hi) {
    ull r; asm("mov.b64 %0, {%1, %2};" : "=l"(r) : "f"(lo), "f"(hi)); return r;
}
__device__ __forceinline__ ull fma2(ull a, ull b, ull c) {
    ull d; asm("fma.rn.f32x2 %0, %1, %2, %3;" : "=l"(d) : "l"(a), "l"(b), "l"(c)); return d;
}
__device__ __forceinline__ float pairsum(ull a) {
    float lo, hi; asm("mov.b64 {%0, %1}, %2;" : "=f"(lo), "=f"(hi) : "l"(a)); return lo + hi;
}
__device__ __forceinline__ void prefetchL2(const void* p) {
    asm volatile("prefetch.global.L2 [%0];" :: "l"(p));
}

// ---------------- device scratch (no allocation allowed) ----------------
__device__ float g_partial[NB*NCHUNK*H];   // fully overwritten each call
__device__ float g_h1p[NB*8*HH];
__device__ int   g_rank;
__device__ unsigned g_done = 0;            // gemv completion counter (self-resets)

// ---------------- kernel 1: chunked column sums of keys over S ----------
__global__ void k_mean_partial(const float* __restrict__ keys) {
    int b = blockIdx.y, c = blockIdx.x;
    const float4* base = (const float4*)(keys + ((size_t)b * S + (size_t)c * SCHUNK) * H);
    int t = threadIdx.x;
    float4 a = make_float4(0.f, 0.f, 0.f, 0.f);
#pragma unroll 8
    for (int s = 0; s < SCHUNK; s++) {
        float4 v = base[(size_t)s * (H / 4) + t];
        a.x += v.x; a.y += v.y; a.z += v.z; a.w += v.w;
    }
    ((float4*)(g_partial + ((size_t)b * NCHUNK + c) * H))[t] = a;
}

// ------- kernel 2: hidden GEMV; LAST block also runs select -------------
__global__ void k_gemv1(const float* __restrict__ w1, const float* __restrict__ b1,
                        const float* __restrict__ w2, const float* __restrict__ b2) {
    __shared__ float sx[256];
    __shared__ int s_last;
    int jb = blockIdx.x, hc = blockIdx.y, b = blockIdx.z;
    int t = threadIdx.x;
    {
        int h = hc * 256 + t;
        float s0 = 0.f, s1 = 0.f, s2 = 0.f, s3 = 0.f;
#pragma unroll 8
        for (int c = 0; c < NCHUNK; c += 4) {
            s0 += g_partial[((size_t)b * NCHUNK + c + 0) * H + h];
            s1 += g_partial[((size_t)b * NCHUNK + c + 1) * H + h];
            s2 += g_partial[((size_t)b * NCHUNK + c + 2) * H + h];
            s3 += g_partial[((size_t)b * NCHUNK + c + 3) * H + h];
        }
        sx[t] = (s0 + s1 + s2 + s3) * (1.0f / (float)S);
    }
    __syncthreads();
    int j = jb * 256 + t;
    const float* wp = w1 + (size_t)(hc * 256) * HH + j;
    float a0 = 0.f, a1 = 0.f, a2 = 0.f, a3 = 0.f;
#pragma unroll 8
    for (int hh = 0; hh < 256; hh += 4) {
        a0 = fmaf(sx[hh + 0], wp[(size_t)(hh + 0) * HH], a0);
        a1 = fmaf(sx[hh + 1], wp[(size_t)(hh + 1) * HH], a1);
        a2 = fmaf(sx[hh + 2], wp[(size_t)(hh + 2) * HH], a2);
        a3 = fmaf(sx[hh + 3], wp[(size_t)(hh + 3) * HH], a3);
    }
    g_h1p[((size_t)b * 8 + hc) * HH + j] = (a0 + a1) + (a2 + a3);

    __threadfence();
    if (t == 0) {
        unsigned v = atomicAdd(&g_done, 1u);
        s_last = (v == (4u * 8u * NB - 1u));
        if (s_last) g_done = 0;           // reset for next graph replay
    }
    __syncthreads();
    if (!s_last) return;

    __shared__ float red[256];
    __shared__ float s_avg;
    if (t == 0) s_avg = 0.f;
    __syncthreads();
    for (int bb = 0; bb < NB; bb++) {
        float acc = 0.f;
#pragma unroll
        for (int k = 0; k < 4; k++) {
            int jj = t + k * 256;
            float hv = b1[jj];
#pragma unroll
            for (int hcc = 0; hcc < 8; hcc++) hv += g_h1p[((size_t)bb * 8 + hcc) * HH + jj];
            acc += fmaxf(hv, 0.f) * w2[jj];
        }
        red[t] = acc;
        __syncthreads();
        for (int o = 128; o > 0; o >>= 1) {
            if (t < o) red[t] += red[t + o];
            __syncthreads();
        }
        if (t == 0) {
            float v = red[0] + b2[0];
            s_avg += 1.f / (1.f + expf(-v));
        }
        __syncthreads();
    }
    if (t == 0) {
        float avg = s_avg * 0.25f;
        g_rank = (int)(avg >= 0.3f) + (int)(avg >= 0.7f);
    }
}

// ======================= persistent main kernel ==========================
// smem: s_w = 8*H floats (A^T, staged once per CTA), s_P2 = 2 x 32*16*2.

template <int R>
__device__ __forceinline__ void phase1(
    const float* __restrict__ src, int row0, const float* s_w, float* s_P2) {
    int tid = threadIdx.x;
    int w = tid >> 5, l = tid & 31;
    ull acc[4][R];
#pragma unroll
    for (int i = 0; i < 4; i++)
#pragma unroll
        for (int j = 0; j < R; j++) acc[i][j] = 0ull;

    const ulonglong2* rp0 = (const ulonglong2*)(src + (size_t)(row0 + w * 4 + 0) * H);
    const ulonglong2* rp1 = (const ulonglong2*)(src + (size_t)(row0 + w * 4 + 1) * H);
    const ulonglong2* rp2 = (const ulonglong2*)(src + (size_t)(row0 + w * 4 + 2) * H);
    const ulonglong2* rp3 = (const ulonglong2*)(src + (size_t)(row0 + w * 4 + 3) * H);

#pragma unroll 2
    for (int h4 = l; h4 < H / 4; h4 += 32) {
        ulonglong2 k0 = rp0[h4], k1 = rp1[h4], k2 = rp2[h4], k3 = rp3[h4];
#pragma unroll
        for (int j = 0; j < R; j++) {
            ulonglong2 aq = *(const ulonglong2*)(s_w + j * H + h4 * 4);
            acc[0][j] = fma2(k0.x, aq.x, acc[0][j]);
            acc[0][j] = fma2(k0.y, aq.y, acc[0][j]);
            acc[1][j] = fma2(k1.x, aq.x, acc[1][j]);
            acc[1][j] = fma2(k1.y, aq.y, acc[1][j]);
            acc[2][j] = fma2(k2.x, aq.x, acc[2][j]);
            acc[2][j] = fma2(k2.y, aq.y, acc[2][j]);
            acc[3][j] = fma2(k3.x, aq.x, acc[3][j]);
            acc[3][j] = fma2(k3.y, aq.y, acc[3][j]);
        }
    }
#pragma unroll
    for (int i = 0; i < 4; i++)
#pragma unroll
        for (int j = 0; j < R; j++) {
            float v = pairsum(acc[i][j]);
#pragma unroll
            for (int o = 16; o > 0; o >>= 1) v += __shfl_xor_sync(0xffffffffu, v, o);
            if (l == 0) *(ull*)(s_P2 + ((w * 4 + i) * R + j) * 2) = pack2(v, v);
        }
}

template <int R>
__device__ __forceinline__ void phase2(
    const float* __restrict__ src, const float* __restrict__ Bw,
    float* __restrict__ dst, int row0, const float* s_P2,
    const float* __restrict__ pf, bool do_pf) {
    int tid = threadIdx.x;

    // prefetch next tile's rows into L2 (2048 lines of 128B, 8 per thread)
    if (do_pf) {
#pragma unroll
        for (int i = 0; i < 8; i++)
            prefetchL2(pf + (size_t)(i * MT + tid) * 32);
    }

#pragma unroll
    for (int cs = 0; cs < 2; cs++) {
        int col4 = tid + cs * MT;
        ull b0[R], b1[R];
#pragma unroll
        for (int j = 0; j < R; j++) {
            float4 bv = __ldg((const float4*)(Bw + (size_t)j * H + col4 * 4));
            b0[j] = pack2(bv.x, bv.y); b1[j] = pack2(bv.z, bv.w);
        }
#pragma unroll 1
        for (int g = 0; g < TILE_R; g += 4) {
            float4 v0 = *((const float4*)(src + (size_t)(row0 + g + 0) * H) + col4);
            float4 v1 = *((const float4*)(src + (size_t)(row0 + g + 1) * H) + col4);
            float4 v2 = *((const float4*)(src + (size_t)(row0 + g + 2) * H) + col4);
            float4 v3 = *((const float4*)(src + (size_t)(row0 + g + 3) * H) + col4);
            ull o0x = pack2(v0.x, v0.y), o0y = pack2(v0.z, v0.w);
            ull o1x = pack2(v1.x, v1.y), o1y = pack2(v1.z, v1.w);
            ull o2x = pack2(v2.x, v2.y), o2y = pack2(v2.z, v2.w);
            ull o3x = pack2(v3.x, v3.y), o3y = pack2(v3.z, v3.w);
#pragma unroll
            for (int j = 0; j < R; j += 2) {   // LDS.128 pulls p for (j, j+1)
                ulonglong2 q0 = *(const ulonglong2*)(s_P2 + ((g + 0) * R + j) * 2);
                ulonglong2 q1 = *(const ulonglong2*)(s_P2 + ((g + 1) * R + j) * 2);
                ulonglong2 q2 = *(const ulonglong2*)(s_P2 + ((g + 2) * R + j) * 2);
                ulonglong2 q3 = *(const ulonglong2*)(s_P2 + ((g + 3) * R + j) * 2);
                o0x = fma2(b0[j], q0.x, o0x); o0y = fma2(b1[j], q0.x, o0y);
                o1x = fma2(b0[j], q1.x, o1x); o1y = fma2(b1[j], q1.x, o1y);
                o2x = fma2(b0[j], q2.x, o2x); o2y = fma2(b1[j], q2.x, o2y);
                o3x = fma2(b0[j], q3.x, o3x); o3y = fma2(b1[j], q3.x, o3y);
                o0x = fma2(b0[j+1], q0.y, o0x); o0y = fma2(b1[j+1], q0.y, o0y);
                o1x = fma2(b0[j+1], q1.y, o1x); o1y = fma2(b1[j+1], q1.y, o1y);
                o2x = fma2(b0[j+1], q2.y, o2x); o2y = fma2(b1[j+1], q2.y, o2y);
                o3x = fma2(b0[j+1], q3.y, o3x); o3y = fma2(b1[j+1], q3.y, o3y);
            }
            float r0, r1, r2, r3;
#define STORE_ROW(OX, OY, GG)                                                \
            asm("mov.b64 {%0, %1}, %2;" : "=f"(r0), "=f"(r1) : "l"(OX));     \
            asm("mov.b64 {%0, %1}, %2;" : "=f"(r2), "=f"(r3) : "l"(OY));     \
            *((float4*)(dst + (size_t)(row0 + GG) * H) + col4) =             \
                make_float4(r0, r1, r2, r3);
            STORE_ROW(o0x, o0y, g + 0)
            STORE_ROW(o1x, o1y, g + 1)
            STORE_ROW(o2x, o2y, g + 2)
            STORE_ROW(o3x, o3y, g + 3)
#undef STORE_ROW
        }
    }
}

// hot persistent body: A^T staged once; double-buffered P; ONE bar/tile
template <int R>
__device__ __forceinline__ void run_half(
    const float* __restrict__ src, const float* __restrict__ A,
    const float* __restrict__ Bw, float* __restrict__ dst,
    int t0, float* s_w, float* s_P2) {

    constexpr int SH = (R == 4) ? 2 : 3;
    constexpr int PB = TILE_R * R * 2;
    int tid = threadIdx.x;
    for (int idx = tid; idx < H * R; idx += MT) {
        int h = idx >> SH, j = idx & (R - 1);
        s_w[j * H + h] = A[idx];
    }
    __syncthreads();

    int buf = 0;
    for (int t = t0; t < NTILE; t += CTAS_HALF) {
        int nt = t + CTAS_HALF;
        phase1<R>(src, t * TILE_R, s_w, s_P2 + buf * PB);
        __syncthreads();
        phase2<R>(src, Bw, dst, t * TILE_R, s_P2 + buf * PB,
                  src + (size_t)nt * TILE_R * H, nt < NTILE);
        buf ^= 1;   // no trailing barrier: next phase1 writes the other buffer
    }
}

// ---- cold path: R = 16, per-tile staged halves (correct, never hot) ----
__device__ __noinline__ void tile16(
    const float* __restrict__ src, const float* __restrict__ A,
    const float* __restrict__ Bw, float* __restrict__ dst,
    int row0, float* s_w, float* s_P2) {
    int tid = threadIdx.x;
    int w = tid >> 5, l = tid & 31;
    constexpr int R = 16;
    for (int half = 0; half < 2; half++) {
        for (int idx = tid; idx < H * 8; idx += MT) {
            int h = idx >> 3, j = idx & 7;
            s_w[j * H + h] = A[(size_t)h * R + half * 8 + j];
        }
        __syncthreads();
        for (int ps = 0; ps < 2; ps++) {
            int rb = ps * 16 + w * 2;
            ull acc[2][8];
#pragma unroll
            for (int i = 0; i < 2; i++)
#pragma unroll
                for (int j = 0; j < 8; j++) acc[i][j] = 0ull;
            const ulonglong2* rp0 = (const ulonglong2*)(src + (size_t)(row0 + rb + 0) * H);
            const ulonglong2* rp1 = (const ulonglong2*)(src + (size_t)(row0 + rb + 1) * H);
            for (int h4 = l; h4 < H / 4; h4 += 32) {
                ulonglong2 k0 = rp0[h4], k1 = rp1[h4];
#pragma unroll
                for (int j = 0; j < 8; j++) {
                    ulonglong2 aq = *(const ulonglong2*)(s_w + j * H + h4 * 4);
                    acc[0][j] = fma2(k0.x, aq.x, acc[0][j]);
                    acc[0][j] = fma2(k0.y, aq.y, acc[0][j]);
                    acc[1][j] = fma2(k1.x, aq.x, acc[1][j]);
                    acc[1][j] = fma2(k1.y, aq.y, acc[1][j]);
                }
            }
#pragma unroll
            for (int i = 0; i < 2; i++)
#pragma unroll
                for (int j = 0; j < 8; j++) {
                    float v = pairsum(acc[i][j]);
#pragma unroll
                    for (int o = 16; o > 0; o >>= 1) v += __shfl_xor_sync(0xffffffffu, v, o);
                    if (l == 0)
                        *(ull*)(s_P2 + ((rb + i) * R + half * 8 + j) * 2) = pack2(v, v);
                }
        }
        __syncthreads();
    }
    for (int cs = 0; cs < 2; cs++) {
        int col4 = tid + cs * MT;
        for (int g = 0; g < TILE_R; g += 2) {
            float4 v0 = *((const float4*)(src + (size_t)(row0 + g + 0) * H) + col4);
            float4 v1 = *((const float4*)(src + (size_t)(row0 + g + 1) * H) + col4);
            ull o0x = pack2(v0.x, v0.y), o0y = pack2(v0.z, v0.w);
            ull o1x = pack2(v1.x, v1.y), o1y = pack2(v1.z, v1.w);
#pragma unroll
            for (int j = 0; j < R; j++) {
                float4 bv = __ldg((const float4*)(Bw + (size_t)j * H + col4 * 4));
                ull bx = pack2(bv.x, bv.y), by = pack2(bv.z, bv.w);
                ull p0 = *(const ull*)(s_P2 + ((g + 0) * R + j) * 2);
                ull p1 = *(const ull*)(s_P2 + ((g + 1) * R + j) * 2);
                o0x = fma2(bx, p0, o0x); o0y = fma2(by, p0, o0y);
                o1x = fma2(bx, p1, o1x); o1y = fma2(by, p1, o1y);
            }
            float r0, r1, r2, r3;
            asm("mov.b64 {%0, %1}, %2;" : "=f"(r0), "=f"(r1) : "l"(o0x));
            asm("mov.b64 {%0, %1}, %2;" : "=f"(r2), "=f"(r3) : "l"(o0y));
            *((float4*)(dst + (size_t)(row0 + g + 0) * H) + col4) = make_float4(r0, r1, r2, r3);
            asm("mov.b64 {%0, %1}, %2;" : "=f"(r0), "=f"(r1) : "l"(o1x));
            asm("mov.b64 {%0, %1}, %2;" : "=f"(r2), "=f"(r3) : "l"(o1y));
            *((float4*)(dst + (size_t)(row0 + g + 1) * H) + col4) = make_float4(r0, r1, r2, r3);
        }
    }
}

__global__ void __launch_bounds__(MT, 2)
k_main_all(const float* __restrict__ keys, const float* __restrict__ values,
           const float* __restrict__ kA0, const float* __restrict__ kB0,
           const float* __restrict__ vA0, const float* __restrict__ vB0,
           const float* __restrict__ kA1, const float* __restrict__ kB1,
           const float* __restrict__ vA1, const float* __restrict__ vB1,
           const float* __restrict__ kA2, const float* __restrict__ kB2,
           const float* __restrict__ vA2, const float* __restrict__ vB2,
           float* __restrict__ out) {
    extern __shared__ float smem[];
    float* s_w  = smem;                 // 8*H floats
    float* s_P2 = smem + 8 * H;         // 2 buffers of 32*16*2 floats

    int r = g_rank;
    bool is_k = (blockIdx.x < CTAS_HALF);
    // complementary tile-count pairing: co-resident CTAs (bid, bid+CTAS_HALF)
    int t0 = is_k ? blockIdx.x : (CTAS_HALF - 1) - (blockIdx.x - CTAS_HALF);
    const float* src = is_k ? keys : values;
    float* dst = is_k ? out : out + (size_t)NROWS * H;

    if (r == 0)
        run_half<4>(src, is_k ? kA0 : vA0, is_k ? kB0 : vB0, dst, t0, s_w, s_P2);
    else if (r == 1)
        run_half<8>(src, is_k ? kA1 : vA1, is_k ? kB1 : vB1, dst, t0, s_w, s_P2);
    else {
        const float* A = is_k ? kA2 : vA2;
        const float* B = is_k ? kB2 : vB2;
        for (int t = t0; t < NTILE; t += CTAS_HALF) {
            tile16(src, A, B, dst, t * TILE_R, s_w, s_P2);
            __syncthreads();
        }
    }
}

// ---------------- launch -------------------------------------------------
extern "C" void kernel_launch(void* const* d_in, const int* in_sizes, int n_in,
                              void* d_out, int out_size) {
    const float* keys   = (const float*)d_in[0];
    const float* values = (const float*)d_in[1];
    const float* w1     = (const float*)d_in[2];
    const float* b1     = (const float*)d_in[3];
    const float* w2     = (const float*)d_in[4];
    const float* b2     = (const float*)d_in[5];
    const float* kA0 = (const float*)d_in[6];  const float* kB0 = (const float*)d_in[7];
    const float* vA0 = (const float*)d_in[8];  const float* vB0 = (const float*)d_in[9];
    const float* kA1 = (const float*)d_in[10]; const float* kB1 = (const float*)d_in[11];
    const float* vA1 = (const float*)d_in[12]; const float* vB1 = (const float*)d_in[13];
    const float* kA2 = (const float*)d_in[14]; const float* kB2 = (const float*)d_in[15];
    const float* vA2 = (const float*)d_in[16]; const float* vB2 = (const float*)d_in[17];
    float* out = (float*)d_out;

    const int smem_bytes = (8 * H + 2 * TILE_R * 16 * 2) * (int)sizeof(float);  // 73,728
    cudaFuncSetAttribute(k_main_all, cudaFuncAttributeMaxDynamicSharedMemorySize, smem_bytes);

    k_mean_partial<<<dim3(NCHUNK, NB), 512>>>(keys);
    k_gemv1<<<dim3(4, 8, NB), 256>>>(w1, b1, w2, b2);

    k_main_all<<<2 * CTAS_HALF, MT, smem_bytes>>>(
        keys, values,
        kA0, kB0, vA0, vB0,
        kA1, kB1, vA1, vB1,
        kA2, kB2, vA2, vB2,
        out);
}

// round 15
// speedup vs baseline: 1.0908x; 1.0908x over previous
#include <cuda_runtime.h>
#include <math.h>

#define H      2048
#define HH     1024
#define NB     4
#define S      4096
#define NROWS  (NB*S)          // 16384 rows per matrix
#define SCHUNK 32
#define NCHUNK (S/SCHUNK)      // 128
#define TILE_R 32
#define NTILE  (NROWS/TILE_R)  // 512 tiles per half
#define CTAS_HALF 152
#define MT     256             // main kernel threads

typedef unsigned long long ull;

// ---------------- packed f32x2 helpers ----------------------------------
__device__ __forceinline__ ull pack2(float lo, float hi) {
    ull r; asm("mov.b64 %0, {%1, %2};" : "=l"(r) : "f"(lo), "f"(hi)); return r;
}
__device__ __forceinline__ ull fma2(ull a, ull b, ull c) {
    ull d; asm("fma.rn.f32x2 %0, %1, %2, %3;" : "=l"(d) : "l"(a), "l"(b), "l"(c)); return d;
}
__device__ __forceinline__ float pairsum(ull a) {
    float lo, hi; asm("mov.b64 {%0, %1}, %2;" : "=f"(lo), "=f"(hi) : "l"(a)); return lo + hi;
}

// ---------------- device scratch (no allocation allowed) ----------------
__device__ float g_partial[NB*NCHUNK*H];   // fully overwritten each call
__device__ float g_h1p[NB*8*HH];
__device__ int   g_rank;
__device__ unsigned g_done = 0;            // gemv completion counter (self-resets)

// ---------------- kernel 1: chunked column sums of keys over S ----------
__global__ void k_mean_partial(const float* __restrict__ keys) {
    int b = blockIdx.y, c = blockIdx.x;
    const float4* base = (const float4*)(keys + ((size_t)b * S + (size_t)c * SCHUNK) * H);
    int t = threadIdx.x;
    float4 a = make_float4(0.f, 0.f, 0.f, 0.f);
#pragma unroll 8
    for (int s = 0; s < SCHUNK; s++) {
        float4 v = base[(size_t)s * (H / 4) + t];
        a.x += v.x; a.y += v.y; a.z += v.z; a.w += v.w;
    }
    ((float4*)(g_partial + ((size_t)b * NCHUNK + c) * H))[t] = a;
}

// ------- kernel 2: hidden GEMV; LAST block also runs select -------------
__global__ void k_gemv1(const float* __restrict__ w1, const float* __restrict__ b1,
                        const float* __restrict__ w2, const float* __restrict__ b2) {
    __shared__ float sx[256];
    __shared__ int s_last;
    int jb = blockIdx.x, hc = blockIdx.y, b = blockIdx.z;
    int t = threadIdx.x;
    {
        int h = hc * 256 + t;
        float s0 = 0.f, s1 = 0.f, s2 = 0.f, s3 = 0.f;
#pragma unroll 8
        for (int c = 0; c < NCHUNK; c += 4) {
            s0 += g_partial[((size_t)b * NCHUNK + c + 0) * H + h];
            s1 += g_partial[((size_t)b * NCHUNK + c + 1) * H + h];
            s2 += g_partial[((size_t)b * NCHUNK + c + 2) * H + h];
            s3 += g_partial[((size_t)b * NCHUNK + c + 3) * H + h];
        }
        sx[t] = (s0 + s1 + s2 + s3) * (1.0f / (float)S);
    }
    __syncthreads();
    int j = jb * 256 + t;
    const float* wp = w1 + (size_t)(hc * 256) * HH + j;
    float a0 = 0.f, a1 = 0.f, a2 = 0.f, a3 = 0.f;
#pragma unroll 8
    for (int hh = 0; hh < 256; hh += 4) {
        a0 = fmaf(sx[hh + 0], wp[(size_t)(hh + 0) * HH], a0);
        a1 = fmaf(sx[hh + 1], wp[(size_t)(hh + 1) * HH], a1);
        a2 = fmaf(sx[hh + 2], wp[(size_t)(hh + 2) * HH], a2);
        a3 = fmaf(sx[hh + 3], wp[(size_t)(hh + 3) * HH], a3);
    }
    g_h1p[((size_t)b * 8 + hc) * HH + j] = (a0 + a1) + (a2 + a3);

    __threadfence();
    if (t == 0) {
        unsigned v = atomicAdd(&g_done, 1u);
        s_last = (v == (4u * 8u * NB - 1u));
        if (s_last) g_done = 0;           // reset for next graph replay
    }
    __syncthreads();
    if (!s_last) return;

    __shared__ float red[256];
    __shared__ float s_avg;
    if (t == 0) s_avg = 0.f;
    __syncthreads();
    for (int bb = 0; bb < NB; bb++) {
        float acc = 0.f;
#pragma unroll
        for (int k = 0; k < 4; k++) {
            int jj = t + k * 256;
            float hv = b1[jj];
#pragma unroll
            for (int hcc = 0; hcc < 8; hcc++) hv += g_h1p[((size_t)bb * 8 + hcc) * HH + jj];
            acc += fmaxf(hv, 0.f) * w2[jj];
        }
        red[t] = acc;
        __syncthreads();
        for (int o = 128; o > 0; o >>= 1) {
            if (t < o) red[t] += red[t + o];
            __syncthreads();
        }
        if (t == 0) {
            float v = red[0] + b2[0];
            s_avg += 1.f / (1.f + expf(-v));
        }
        __syncthreads();
    }
    if (t == 0) {
        float avg = s_avg * 0.25f;
        g_rank = (int)(avg >= 0.3f) + (int)(avg >= 0.7f);
    }
}

// ======================= persistent main kernel ==========================
// smem: s_w = 8*H floats (A^T, staged once per CTA), s_P2 = 2 x 32*16*2.

template <int R>
__device__ __forceinline__ void phase1(
    const float* __restrict__ src, int row0, const float* s_w, float* s_P2) {
    int tid = threadIdx.x;
    int w = tid >> 5, l = tid & 31;
    ull acc[4][R];
#pragma unroll
    for (int i = 0; i < 4; i++)
#pragma unroll
        for (int j = 0; j < R; j++) acc[i][j] = 0ull;

    const ulonglong2* rp0 = (const ulonglong2*)(src + (size_t)(row0 + w * 4 + 0) * H);
    const ulonglong2* rp1 = (const ulonglong2*)(src + (size_t)(row0 + w * 4 + 1) * H);
    const ulonglong2* rp2 = (const ulonglong2*)(src + (size_t)(row0 + w * 4 + 2) * H);
    const ulonglong2* rp3 = (const ulonglong2*)(src + (size_t)(row0 + w * 4 + 3) * H);

#pragma unroll 2
    for (int h4 = l; h4 < H / 4; h4 += 32) {
        ulonglong2 k0 = rp0[h4], k1 = rp1[h4], k2 = rp2[h4], k3 = rp3[h4];
#pragma unroll
        for (int j = 0; j < R; j++) {
            ulonglong2 aq = *(const ulonglong2*)(s_w + j * H + h4 * 4);
            acc[0][j] = fma2(k0.x, aq.x, acc[0][j]);
            acc[0][j] = fma2(k0.y, aq.y, acc[0][j]);
            acc[1][j] = fma2(k1.x, aq.x, acc[1][j]);
            acc[1][j] = fma2(k1.y, aq.y, acc[1][j]);
            acc[2][j] = fma2(k2.x, aq.x, acc[2][j]);
            acc[2][j] = fma2(k2.y, aq.y, acc[2][j]);
            acc[3][j] = fma2(k3.x, aq.x, acc[3][j]);
            acc[3][j] = fma2(k3.y, aq.y, acc[3][j]);
        }
    }
#pragma unroll
    for (int i = 0; i < 4; i++)
#pragma unroll
        for (int j = 0; j < R; j++) {
            float v = pairsum(acc[i][j]);
#pragma unroll
            for (int o = 16; o > 0; o >>= 1) v += __shfl_xor_sync(0xffffffffu, v, o);
            if (l == 0) *(ull*)(s_P2 + ((w * 4 + i) * R + j) * 2) = pack2(v, v);
        }
}

template <int R>
__device__ __forceinline__ void phase2(
    const float* __restrict__ src, const float* __restrict__ Bw,
    float* __restrict__ dst, int row0, const float* s_P2) {
    int tid = threadIdx.x;
#pragma unroll
    for (int cs = 0; cs < 2; cs++) {
        int col4 = tid + cs * MT;
        ull b0[R], b1[R];
#pragma unroll
        for (int j = 0; j < R; j++) {
            float4 bv = __ldg((const float4*)(Bw + (size_t)j * H + col4 * 4));
            b0[j] = pack2(bv.x, bv.y); b1[j] = pack2(bv.z, bv.w);
        }
#pragma unroll 1
        for (int g = 0; g < TILE_R; g += 4) {
            float4 v0 = *((const float4*)(src + (size_t)(row0 + g + 0) * H) + col4);
            float4 v1 = *((const float4*)(src + (size_t)(row0 + g + 1) * H) + col4);
            float4 v2 = *((const float4*)(src + (size_t)(row0 + g + 2) * H) + col4);
            float4 v3 = *((const float4*)(src + (size_t)(row0 + g + 3) * H) + col4);
            ull o0x = pack2(v0.x, v0.y), o0y = pack2(v0.z, v0.w);
            ull o1x = pack2(v1.x, v1.y), o1y = pack2(v1.z, v1.w);
            ull o2x = pack2(v2.x, v2.y), o2y = pack2(v2.z, v2.w);
            ull o3x = pack2(v3.x, v3.y), o3y = pack2(v3.z, v3.w);
#pragma unroll
            for (int j = 0; j < R; j += 2) {   // LDS.128 pulls p for (j, j+1)
                ulonglong2 q0 = *(const ulonglong2*)(s_P2 + ((g + 0) * R + j) * 2);
                ulonglong2 q1 = *(const ulonglong2*)(s_P2 + ((g + 1) * R + j) * 2);
                ulonglong2 q2 = *(const ulonglong2*)(s_P2 + ((g + 2) * R + j) * 2);
                ulonglong2 q3 = *(const ulonglong2*)(s_P2 + ((g + 3) * R + j) * 2);
                o0x = fma2(b0[j], q0.x, o0x); o0y = fma2(b1[j], q0.x, o0y);
                o1x = fma2(b0[j], q1.x, o1x); o1y = fma2(b1[j], q1.x, o1y);
                o2x = fma2(b0[j], q2.x, o2x); o2y = fma2(b1[j], q2.x, o2y);
                o3x = fma2(b0[j], q3.x, o3x); o3y = fma2(b1[j], q3.x, o3y);
                o0x = fma2(b0[j+1], q0.y, o0x); o0y = fma2(b1[j+1], q0.y, o0y);
                o1x = fma2(b0[j+1], q1.y, o1x); o1y = fma2(b1[j+1], q1.y, o1y);
                o2x = fma2(b0[j+1], q2.y, o2x); o2y = fma2(b1[j+1], q2.y, o2y);
                o3x = fma2(b0[j+1], q3.y, o3x); o3y = fma2(b1[j+1], q3.y, o3y);
            }
            float r0, r1, r2, r3;
#define STORE_ROW(OX, OY, GG)                                                \
            asm("mov.b64 {%0, %1}, %2;" : "=f"(r0), "=f"(r1) : "l"(OX));     \
            asm("mov.b64 {%0, %1}, %2;" : "=f"(r2), "=f"(r3) : "l"(OY));     \
            *((float4*)(dst + (size_t)(row0 + GG) * H) + col4) =             \
                make_float4(r0, r1, r2, r3);
            STORE_ROW(o0x, o0y, g + 0)
            STORE_ROW(o1x, o1y, g + 1)
            STORE_ROW(o2x, o2y, g + 2)
            STORE_ROW(o3x, o3y, g + 3)
#undef STORE_ROW
        }
    }
}

// hot persistent body: A^T staged once; double-buffered P; ONE bar/tile
template <int R>
__device__ __forceinline__ void run_half(
    const float* __restrict__ src, const float* __restrict__ A,
    const float* __restrict__ Bw, float* __restrict__ dst,
    int t0, float* s_w, float* s_P2) {

    constexpr int SH = (R == 4) ? 2 : 3;
    constexpr int PB = TILE_R * R * 2;
    int tid = threadIdx.x;
    for (int idx = tid; idx < H * R; idx += MT) {
        int h = idx >> SH, j = idx & (R - 1);
        s_w[j * H + h] = A[idx];
    }
    __syncthreads();

    int buf = 0;
    for (int t = t0; t < NTILE; t += CTAS_HALF) {
        phase1<R>(src, t * TILE_R, s_w, s_P2 + buf * PB);
        __syncthreads();
        phase2<R>(src, Bw, dst, t * TILE_R, s_P2 + buf * PB);
        buf ^= 1;   // no trailing barrier: next phase1 writes the other buffer
    }
}

// ---- cold path: R = 16, per-tile staged halves (correct, never hot) ----
__device__ __noinline__ void tile16(
    const float* __restrict__ src, const float* __restrict__ A,
    const float* __restrict__ Bw, float* __restrict__ dst,
    int row0, float* s_w, float* s_P2) {
    int tid = threadIdx.x;
    int w = tid >> 5, l = tid & 31;
    constexpr int R = 16;
    for (int half = 0; half < 2; half++) {
        for (int idx = tid; idx < H * 8; idx += MT) {
            int h = idx >> 3, j = idx & 7;
            s_w[j * H + h] = A[(size_t)h * R + half * 8 + j];
        }
        __syncthreads();
        for (int ps = 0; ps < 2; ps++) {
            int rb = ps * 16 + w * 2;
            ull acc[2][8];
#pragma unroll
            for (int i = 0; i < 2; i++)
#pragma unroll
                for (int j = 0; j < 8; j++) acc[i][j] = 0ull;
            const ulonglong2* rp0 = (const ulonglong2*)(src + (size_t)(row0 + rb + 0) * H);
            const ulonglong2* rp1 = (const ulonglong2*)(src + (size_t)(row0 + rb + 1) * H);
            for (int h4 = l; h4 < H / 4; h4 += 32) {
                ulonglong2 k0 = rp0[h4], k1 = rp1[h4];
#pragma unroll
                for (int j = 0; j < 8; j++) {
                    ulonglong2 aq = *(const ulonglong2*)(s_w + j * H + h4 * 4);
                    acc[0][j] = fma2(k0.x, aq.x, acc[0][j]);
                    acc[0][j] = fma2(k0.y, aq.y, acc[0][j]);
                    acc[1][j] = fma2(k1.x, aq.x, acc[1][j]);
                    acc[1][j] = fma2(k1.y, aq.y, acc[1][j]);
                }
            }
#pragma unroll
            for (int i = 0; i < 2; i++)
#pragma unroll
                for (int j = 0; j < 8; j++) {
                    float v = pairsum(acc[i][j]);
#pragma unroll
                    for (int o = 16; o > 0; o >>= 1) v += __shfl_xor_sync(0xffffffffu, v, o);
                    if (l == 0)
                        *(ull*)(s_P2 + ((rb + i) * R + half * 8 + j) * 2) = pack2(v, v);
                }
        }
        __syncthreads();
    }
    for (int cs = 0; cs < 2; cs++) {
        int col4 = tid + cs * MT;
        for (int g = 0; g < TILE_R; g += 2) {
            float4 v0 = *((const float4*)(src + (size_t)(row0 + g + 0) * H) + col4);
            float4 v1 = *((const float4*)(src + (size_t)(row0 + g + 1) * H) + col4);
            ull o0x = pack2(v0.x, v0.y), o0y = pack2(v0.z, v0.w);
            ull o1x = pack2(v1.x, v1.y), o1y = pack2(v1.z, v1.w);
#pragma unroll
            for (int j = 0; j < R; j++) {
                float4 bv = __ldg((const float4*)(Bw + (size_t)j * H + col4 * 4));
                ull bx = pack2(bv.x, bv.y), by = pack2(bv.z, bv.w);
                ull p0 = *(const ull*)(s_P2 + ((g + 0) * R + j) * 2);
                ull p1 = *(const ull*)(s_P2 + ((g + 1) * R + j) * 2);
                o0x = fma2(bx, p0, o0x); o0y = fma2(by, p0, o0y);
                o1x = fma2(bx, p1, o1x); o1y = fma2(by, p1, o1y);
            }
            float r0, r1, r2, r3;
            asm("mov.b64 {%0, %1}, %2;" : "=f"(r0), "=f"(r1) : "l"(o0x));
            asm("mov.b64 {%0, %1}, %2;" : "=f"(r2), "=f"(r3) : "l"(o0y));
            *((float4*)(dst + (size_t)(row0 + g + 0) * H) + col4) = make_float4(r0, r1, r2, r3);
            asm("mov.b64 {%0, %1}, %2;" : "=f"(r0), "=f"(r1) : "l"(o1x));
            asm("mov.b64 {%0, %1}, %2;" : "=f"(r2), "=f"(r3) : "l"(o1y));
            *((float4*)(dst + (size_t)(row0 + g + 1) * H) + col4) = make_float4(r0, r1, r2, r3);
        }
    }
}

__global__ void __launch_bounds__(MT, 2)
k_main_all(const float* __restrict__ keys, const float* __restrict__ values,
           const float* __restrict__ kA0, const float* __restrict__ kB0,
           const float* __restrict__ vA0, const float* __restrict__ vB0,
           const float* __restrict__ kA1, const float* __restrict__ kB1,
           const float* __restrict__ vA1, const float* __restrict__ vB1,
           const float* __restrict__ kA2, const float* __restrict__ kB2,
           const float* __restrict__ vA2, const float* __restrict__ vB2,
           float* __restrict__ out) {
    extern __shared__ float smem[];
    float* s_w  = smem;                 // 8*H floats
    float* s_P2 = smem + 8 * H;         // 2 buffers of 32*16*2 floats

    int r = g_rank;
    bool is_k = (blockIdx.x < CTAS_HALF);
    // complementary tile-count pairing: co-resident CTAs (bid, bid+CTAS_HALF)
    int t0 = is_k ? blockIdx.x : (CTAS_HALF - 1) - (blockIdx.x - CTAS_HALF);
    const float* src = is_k ? keys : values;
    float* dst = is_k ? out : out + (size_t)NROWS * H;

    if (r == 0)
        run_half<4>(src, is_k ? kA0 : vA0, is_k ? kB0 : vB0, dst, t0, s_w, s_P2);
    else if (r == 1)
        run_half<8>(src, is_k ? kA1 : vA1, is_k ? kB1 : vB1, dst, t0, s_w, s_P2);
    else {
        const float* A = is_k ? kA2 : vA2;
        const float* B = is_k ? kB2 : vB2;
        for (int t = t0; t < NTILE; t += CTAS_HALF) {
            tile16(src, A, B, dst, t * TILE_R, s_w, s_P2);
            __syncthreads();
        }
    }
}

// ---------------- launch -------------------------------------------------
extern "C" void kernel_launch(void* const* d_in, const int* in_sizes, int n_in,
                              void* d_out, int out_size) {
    const float* keys   = (const float*)d_in[0];
    const float* values = (const float*)d_in[1];
    const float* w1     = (const float*)d_in[2];
    const float* b1     = (const float*)d_in[3];
    const float* w2     = (const float*)d_in[4];
    const float* b2     = (const float*)d_in[5];
    const float* kA0 = (const float*)d_in[6];  const float* kB0 = (const float*)d_in[7];
    const float* vA0 = (const float*)d_in[8];  const float* vB0 = (const float*)d_in[9];
    const float* kA1 = (const float*)d_in[10]; const float* kB1 = (const float*)d_in[11];
    const float* vA1 = (const float*)d_in[12]; const float* vB1 = (const float*)d_in[13];
    const float* kA2 = (const float*)d_in[14]; const float* kB2 = (const float*)d_in[15];
    const float* vA2 = (const float*)d_in[16]; const float* vB2 = (const float*)d_in[17];
    float* out = (float*)d_out;

    const int smem_bytes = (8 * H + 2 * TILE_R * 16 * 2) * (int)sizeof(float);  // 73,728
    cudaFuncSetAttribute(k_main_all, cudaFuncAttributeMaxDynamicSharedMemorySize, smem_bytes);

    k_mean_partial<<<dim3(NCHUNK, NB), 512>>>(keys);
    k_gemv1<<<dim3(4, 8, NB), 256>>>(w1, b1, w2, b2);

    k_main_all<<<2 * CTAS_HALF, MT, smem_bytes>>>(
        keys, values,
        kA0, kB0, vA0, vB0,
        kA1, kB1, vA1, vB1,
        kA2, kB2, vA2, vB2,
        out);
}

// round 17
// speedup vs baseline: 1.1702x; 1.0728x over previous
#include <cuda_runtime.h>
#include <math.h>

#define H      2048
#define HH     1024
#define NB     4
#define S      4096
#define NROWS  (NB*S)          // 16384 rows per matrix
#define SCHUNK 32
#define NCHUNK (S/SCHUNK)      // 128
#define TILE_R 32
#define NTILE  (NROWS/TILE_R)  // 512 tiles per half
#define CTAS_HALF 152
#define MT     512             // main kernel threads (16 warps)

typedef unsigned long long ull;

// ---------------- packed f32x2 helpers ----------------------------------
__device__ __forceinline__ ull pack2(float lo, float hi) {
    ull r; asm("mov.b64 %0, {%1, %2};" : "=l"(r) : "f"(lo), "f"(hi)); return r;
}
__device__ __forceinline__ ull fma2(ull a, ull b, ull c) {
    ull d; asm("fma.rn.f32x2 %0, %1, %2, %3;" : "=l"(d) : "l"(a), "l"(b), "l"(c)); return d;
}
__device__ __forceinline__ float pairsum(ull a) {
    float lo, hi; asm("mov.b64 {%0, %1}, %2;" : "=f"(lo), "=f"(hi) : "l"(a)); return lo + hi;
}

// ---------------- device scratch (no allocation allowed) ----------------
__device__ float g_partial[NB*NCHUNK*H];   // fully overwritten each call
__device__ float g_h1p[NB*8*HH];
__device__ int   g_rank;
__device__ unsigned g_done = 0;            // gemv completion counter (self-resets)

// ---------------- kernel 1: chunked column sums of keys over S ----------
__global__ void k_mean_partial(const float* __restrict__ keys) {
    int b = blockIdx.y, c = blockIdx.x;
    const float4* base = (const float4*)(keys + ((size_t)b * S + (size_t)c * SCHUNK) * H);
    int t = threadIdx.x;
    float4 a = make_float4(0.f, 0.f, 0.f, 0.f);
#pragma unroll 8
    for (int s = 0; s < SCHUNK; s++) {
        float4 v = base[(size_t)s * (H / 4) + t];
        a.x += v.x; a.y += v.y; a.z += v.z; a.w += v.w;
    }
    ((float4*)(g_partial + ((size_t)b * NCHUNK + c) * H))[t] = a;
}

// ------- kernel 2: hidden GEMV; LAST block also runs select -------------
__global__ void k_gemv1(const float* __restrict__ w1, const float* __restrict__ b1,
                        const float* __restrict__ w2, const float* __restrict__ b2) {
    __shared__ float sx[256];
    __shared__ int s_last;
    int jb = blockIdx.x, hc = blockIdx.y, b = blockIdx.z;
    int t = threadIdx.x;
    {
        int h = hc * 256 + t;
        float s0 = 0.f, s1 = 0.f, s2 = 0.f, s3 = 0.f;
#pragma unroll 8
        for (int c = 0; c < NCHUNK; c += 4) {
            s0 += g_partial[((size_t)b * NCHUNK + c + 0) * H + h];
            s1 += g_partial[((size_t)b * NCHUNK + c + 1) * H + h];
            s2 += g_partial[((size_t)b * NCHUNK + c + 2) * H + h];
            s3 += g_partial[((size_t)b * NCHUNK + c + 3) * H + h];
        }
        sx[t] = (s0 + s1 + s2 + s3) * (1.0f / (float)S);
    }
    __syncthreads();
    int j = jb * 256 + t;
    const float* wp = w1 + (size_t)(hc * 256) * HH + j;
    float a0 = 0.f, a1 = 0.f, a2 = 0.f, a3 = 0.f;
#pragma unroll 8
    for (int hh = 0; hh < 256; hh += 4) {
        a0 = fmaf(sx[hh + 0], wp[(size_t)(hh + 0) * HH], a0);
        a1 = fmaf(sx[hh + 1], wp[(size_t)(hh + 1) * HH], a1);
        a2 = fmaf(sx[hh + 2], wp[(size_t)(hh + 2) * HH], a2);
        a3 = fmaf(sx[hh + 3], wp[(size_t)(hh + 3) * HH], a3);
    }
    g_h1p[((size_t)b * 8 + hc) * HH + j] = (a0 + a1) + (a2 + a3);

    __threadfence();
    if (t == 0) {
        unsigned v = atomicAdd(&g_done, 1u);
        s_last = (v == (4u * 8u * NB - 1u));
        if (s_last) g_done = 0;           // reset for next graph replay
    }
    __syncthreads();
    if (!s_last) return;

    __shared__ float red[256];
    __shared__ float s_avg;
    if (t == 0) s_avg = 0.f;
    __syncthreads();
    for (int bb = 0; bb < NB; bb++) {
        float acc = 0.f;
#pragma unroll
        for (int k = 0; k < 4; k++) {
            int jj = t + k * 256;
            float hv = b1[jj];
#pragma unroll
            for (int hcc = 0; hcc < 8; hcc++) hv += g_h1p[((size_t)bb * 8 + hcc) * HH + jj];
            acc += fmaxf(hv, 0.f) * w2[jj];
        }
        red[t] = acc;
        __syncthreads();
        for (int o = 128; o > 0; o >>= 1) {
            if (t < o) red[t] += red[t + o];
            __syncthreads();
        }
        if (t == 0) {
            float v = red[0] + b2[0];
            s_avg += 1.f / (1.f + expf(-v));
        }
        __syncthreads();
    }
    if (t == 0) {
        float avg = s_avg * 0.25f;
        g_rank = (int)(avg >= 0.3f) + (int)(avg >= 0.7f);
    }
}

// ======================= persistent main kernel ==========================
// MT=512 (16 warps), 2 CTAs/SM -> 32 warps/SM.
// smem: s_w = 8*H floats (A^T, staged once per CTA), s_P2 = 32*16*2 floats.

// phase 1: 16 warps x 2 rows (covers TILE_R=32 in one pass); acc[2][R]
template <int R>
__device__ __forceinline__ void phase1(
    const float* __restrict__ src, int row0, const float* s_w, float* s_P2) {
    int tid = threadIdx.x;
    int w = tid >> 5, l = tid & 31;
    ull acc[2][R];
#pragma unroll
    for (int i = 0; i < 2; i++)
#pragma unroll
        for (int j = 0; j < R; j++) acc[i][j] = 0ull;

    const ulonglong2* rp0 = (const ulonglong2*)(src + (size_t)(row0 + w * 2 + 0) * H);
    const ulonglong2* rp1 = (const ulonglong2*)(src + (size_t)(row0 + w * 2 + 1) * H);

#pragma unroll 2
    for (int h4 = l; h4 < H / 4; h4 += 32) {
        ulonglong2 k0 = rp0[h4], k1 = rp1[h4];
#pragma unroll
        for (int j = 0; j < R; j++) {
            ulonglong2 aq = *(const ulonglong2*)(s_w + j * H + h4 * 4);
            acc[0][j] = fma2(k0.x, aq.x, acc[0][j]);
            acc[0][j] = fma2(k0.y, aq.y, acc[0][j]);
            acc[1][j] = fma2(k1.x, aq.x, acc[1][j]);
            acc[1][j] = fma2(k1.y, aq.y, acc[1][j]);
        }
    }
#pragma unroll
    for (int i = 0; i < 2; i++)
#pragma unroll
        for (int j = 0; j < R; j++) {
            float v = pairsum(acc[i][j]);
#pragma unroll
            for (int o = 16; o > 0; o >>= 1) v += __shfl_xor_sync(0xffffffffu, v, o);
            if (l == 0) *(ull*)(s_P2 + ((w * 2 + i) * R + j) * 2) = pack2(v, v);
        }
}

// phase 2: thread owns exactly ONE float4 column (H/4 == MT); B in regs
template <int R>
__device__ __forceinline__ void phase2(
    const float* __restrict__ src, const float* __restrict__ Bw,
    float* __restrict__ dst, int row0, const float* s_P2) {
    int col4 = threadIdx.x;
    ull b0[R], b1[R];
#pragma unroll
    for (int j = 0; j < R; j++) {
        float4 bv = __ldg((const float4*)(Bw + (size_t)j * H + col4 * 4));
        b0[j] = pack2(bv.x, bv.y); b1[j] = pack2(bv.z, bv.w);
    }
#pragma unroll 1
    for (int g = 0; g < TILE_R; g += 4) {
        float4 v0 = *((const float4*)(src + (size_t)(row0 + g + 0) * H) + col4);
        float4 v1 = *((const float4*)(src + (size_t)(row0 + g + 1) * H) + col4);
        float4 v2 = *((const float4*)(src + (size_t)(row0 + g + 2) * H) + col4);
        float4 v3 = *((const float4*)(src + (size_t)(row0 + g + 3) * H) + col4);
        ull o0x = pack2(v0.x, v0.y), o0y = pack2(v0.z, v0.w);
        ull o1x = pack2(v1.x, v1.y), o1y = pack2(v1.z, v1.w);
        ull o2x = pack2(v2.x, v2.y), o2y = pack2(v2.z, v2.w);
        ull o3x = pack2(v3.x, v3.y), o3y = pack2(v3.z, v3.w);
#pragma unroll
        for (int j = 0; j < R; j += 2) {   // LDS.128 pulls p for (j, j+1)
            ulonglong2 q0 = *(const ulonglong2*)(s_P2 + ((g + 0) * R + j) * 2);
            ulonglong2 q1 = *(const ulonglong2*)(s_P2 + ((g + 1) * R + j) * 2);
            ulonglong2 q2 = *(const ulonglong2*)(s_P2 + ((g + 2) * R + j) * 2);
            ulonglong2 q3 = *(const ulonglong2*)(s_P2 + ((g + 3) * R + j) * 2);
            o0x = fma2(b0[j], q0.x, o0x); o0y = fma2(b1[j], q0.x, o0y);
            o1x = fma2(b0[j], q1.x, o1x); o1y = fma2(b1[j], q1.x, o1y);
            o2x = fma2(b0[j], q2.x, o2x); o2y = fma2(b1[j], q2.x, o2y);
            o3x = fma2(b0[j], q3.x, o3x); o3y = fma2(b1[j], q3.x, o3y);
            o0x = fma2(b0[j+1], q0.y, o0x); o0y = fma2(b1[j+1], q0.y, o0y);
            o1x = fma2(b0[j+1], q1.y, o1x); o1y = fma2(b1[j+1], q1.y, o1y);
            o2x = fma2(b0[j+1], q2.y, o2x); o2y = fma2(b1[j+1], q2.y, o2y);
            o3x = fma2(b0[j+1], q3.y, o3x); o3y = fma2(b1[j+1], q3.y, o3y);
        }
        float r0, r1, r2, r3;
#define STORE_ROW(OX, OY, GG)                                                \
        asm("mov.b64 {%0, %1}, %2;" : "=f"(r0), "=f"(r1) : "l"(OX));         \
        asm("mov.b64 {%0, %1}, %2;" : "=f"(r2), "=f"(r3) : "l"(OY));         \
        *((float4*)(dst + (size_t)(row0 + GG) * H) + col4) =                 \
            make_float4(r0, r1, r2, r3);
        STORE_ROW(o0x, o0y, g + 0)
        STORE_ROW(o1x, o1y, g + 1)
        STORE_ROW(o2x, o2y, g + 2)
        STORE_ROW(o3x, o3y, g + 3)
#undef STORE_ROW
    }
}

// hot persistent body: A^T staged once; two barriers per tile (R9 proven)
template <int R>
__device__ __forceinline__ void run_half(
    const float* __restrict__ src, const float* __restrict__ A,
    const float* __restrict__ Bw, float* __restrict__ dst,
    int t0, float* s_w, float* s_P2) {

    constexpr int SH = (R == 4) ? 2 : 3;
    int tid = threadIdx.x;
    for (int idx = tid; idx < H * R; idx += MT) {
        int h = idx >> SH, j = idx & (R - 1);
        s_w[j * H + h] = A[idx];
    }
    __syncthreads();

    for (int t = t0; t < NTILE; t += CTAS_HALF) {
        phase1<R>(src, t * TILE_R, s_w, s_P2);
        __syncthreads();
        phase2<R>(src, Bw, dst, t * TILE_R, s_P2);
        __syncthreads();
    }
}

// ---- cold path: R = 16, per-tile staged halves (correct, never hot) ----
__device__ __noinline__ void tile16(
    const float* __restrict__ src, const float* __restrict__ A,
    const float* __restrict__ Bw, float* __restrict__ dst,
    int row0, float* s_w, float* s_P2) {
    int tid = threadIdx.x;
    int w = tid >> 5, l = tid & 31;
    constexpr int R = 16;
    // phase 1 in two j-halves of 8 columns; 16 warps x 2 rows, one pass
    for (int half = 0; half < 2; half++) {
        for (int idx = tid; idx < H * 8; idx += MT) {
            int h = idx >> 3, j = idx & 7;
            s_w[j * H + h] = A[(size_t)h * R + half * 8 + j];
        }
        __syncthreads();
        ull acc[2][8];
#pragma unroll
        for (int i = 0; i < 2; i++)
#pragma unroll
            for (int j = 0; j < 8; j++) acc[i][j] = 0ull;
        const ulonglong2* rp0 = (const ulonglong2*)(src + (size_t)(row0 + w * 2 + 0) * H);
        const ulonglong2* rp1 = (const ulonglong2*)(src + (size_t)(row0 + w * 2 + 1) * H);
        for (int h4 = l; h4 < H / 4; h4 += 32) {
            ulonglong2 k0 = rp0[h4], k1 = rp1[h4];
#pragma unroll
            for (int j = 0; j < 8; j++) {
                ulonglong2 aq = *(const ulonglong2*)(s_w + j * H + h4 * 4);
                acc[0][j] = fma2(k0.x, aq.x, acc[0][j]);
                acc[0][j] = fma2(k0.y, aq.y, acc[0][j]);
                acc[1][j] = fma2(k1.x, aq.x, acc[1][j]);
                acc[1][j] = fma2(k1.y, aq.y, acc[1][j]);
            }
        }
#pragma unroll
        for (int i = 0; i < 2; i++)
#pragma unroll
            for (int j = 0; j < 8; j++) {
                float v = pairsum(acc[i][j]);
#pragma unroll
                for (int o = 16; o > 0; o >>= 1) v += __shfl_xor_sync(0xffffffffu, v, o);
                if (l == 0)
                    *(ull*)(s_P2 + ((w * 2 + i) * R + half * 8 + j) * 2) = pack2(v, v);
            }
        __syncthreads();
    }
    // phase 2: one col per thread, B inline from global (L1/L2-hit)
    {
        int col4 = tid;
        for (int g = 0; g < TILE_R; g += 2) {
            float4 v0 = *((const float4*)(src + (size_t)(row0 + g + 0) * H) + col4);
            float4 v1 = *((const float4*)(src + (size_t)(row0 + g + 1) * H) + col4);
            ull o0x = pack2(v0.x, v0.y), o0y = pack2(v0.z, v0.w);
            ull o1x = pack2(v1.x, v1.y), o1y = pack2(v1.z, v1.w);
#pragma unroll
            for (int j = 0; j < R; j++) {
                float4 bv = __ldg((const float4*)(Bw + (size_t)j * H + col4 * 4));
                ull bx = pack2(bv.x, bv.y), by = pack2(bv.z, bv.w);
                ull p0 = *(const ull*)(s_P2 + ((g + 0) * R + j) * 2);
                ull p1 = *(const ull*)(s_P2 + ((g + 1) * R + j) * 2);
                o0x = fma2(bx, p0, o0x); o0y = fma2(by, p0, o0y);
                o1x = fma2(bx, p1, o1x); o1y = fma2(by, p1, o1y);
            }
            float r0, r1, r2, r3;
            asm("mov.b64 {%0, %1}, %2;" : "=f"(r0), "=f"(r1) : "l"(o0x));
            asm("mov.b64 {%0, %1}, %2;" : "=f"(r2), "=f"(r3) : "l"(o0y));
            *((float4*)(dst + (size_t)(row0 + g + 0) * H) + col4) = make_float4(r0, r1, r2, r3);
            asm("mov.b64 {%0, %1}, %2;" : "=f"(r0), "=f"(r1) : "l"(o1x));
            asm("mov.b64 {%0, %1}, %2;" : "=f"(r2), "=f"(r3) : "l"(o1y));
            *((float4*)(dst + (size_t)(row0 + g + 1) * H) + col4) = make_float4(r0, r1, r2, r3);
        }
    }
}

__global__ void __launch_bounds__(MT, 2)
k_main_all(const float* __restrict__ keys, const float* __restrict__ values,
           const float* __restrict__ kA0, const float* __restrict__ kB0,
           const float* __restrict__ vA0, const float* __restrict__ vB0,
           const float* __restrict__ kA1, const float* __restrict__ kB1,
           const float* __restrict__ vA1, const float* __restrict__ vB1,
           const float* __restrict__ kA2, const float* __restrict__ kB2,
           const float* __restrict__ vA2, const float* __restrict__ vB2,
           float* __restrict__ out) {
    extern __shared__ float smem[];
    float* s_w  = smem;                 // 8*H floats
    float* s_P2 = smem + 8 * H;         // 32*16*2 floats

    int r = g_rank;
    bool is_k = (blockIdx.x < CTAS_HALF);
    // complementary tile-count pairing: co-resident CTAs (bid, bid+CTAS_HALF)
    int t0 = is_k ? blockIdx.x : (CTAS_HALF - 1) - (blockIdx.x - CTAS_HALF);
    const float* src = is_k ? keys : values;
    float* dst = is_k ? out : out + (size_t)NROWS * H;

    if (r == 0)
        run_half<4>(src, is_k ? kA0 : vA0, is_k ? kB0 : vB0, dst, t0, s_w, s_P2);
    else if (r == 1)
        run_half<8>(src, is_k ? kA1 : vA1, is_k ? kB1 : vB1, dst, t0, s_w, s_P2);
    else {
        const float* A = is_k ? kA2 : vA2;
        const float* B = is_k ? kB2 : vB2;
        for (int t = t0; t < NTILE; t += CTAS_HALF) {
            tile16(src, A, B, dst, t * TILE_R, s_w, s_P2);
            __syncthreads();
        }
    }
}

// ---------------- launch -------------------------------------------------
extern "C" void kernel_launch(void* const* d_in, const int* in_sizes, int n_in,
                              void* d_out, int out_size) {
    const float* keys   = (const float*)d_in[0];
    const float* values = (const float*)d_in[1];
    const float* w1     = (const float*)d_in[2];
    const float* b1     = (const float*)d_in[3];
    const float* w2     = (const float*)d_in[4];
    const float* b2     = (const float*)d_in[5];
    const float* kA0 = (const float*)d_in[6];  const float* kB0 = (const float*)d_in[7];
    const float* vA0 = (const float*)d_in[8];  const float* vB0 = (const float*)d_in[9];
    const float* kA1 = (const float*)d_in[10]; const float* kB1 = (const float*)d_in[11];
    const float* vA1 = (const float*)d_in[12]; const float* vB1 = (const float*)d_in[13];
    const float* kA2 = (const float*)d_in[14]; const float* kB2 = (const float*)d_in[15];
    const float* vA2 = (const float*)d_in[16]; const float* vB2 = (const float*)d_in[17];
    float* out = (float*)d_out;

    const int smem_bytes = (8 * H + TILE_R * 16 * 2) * (int)sizeof(float);  // 69,632
    cudaFuncSetAttribute(k_main_all, cudaFuncAttributeMaxDynamicSharedMemorySize, smem_bytes);

    k_mean_partial<<<dim3(NCHUNK, NB), 512>>>(keys);
    k_gemv1<<<dim3(4, 8, NB), 256>>>(w1, b1, w2, b2);

    k_main_all<<<2 * CTAS_HALF, MT, smem_bytes>>>(
        keys, values,
        kA0, kB0, vA0, vB0,
        kA1, kB1, vA1, vB1,
        kA2, kB2, vA2, vB2,
        out);
}